// round 12
// baseline (speedup 1.0000x reference)
#include <cuda_runtime.h>
#include <cuda_fp16.h>
#include <cstdint>

// Problem constants
#define BATCH 8
#define CDIM 512
#define HW   1024
#define NPROTO 150
#define KPROTO 32
#define NK   4800   // NPROTO * KPROTO

// GEMM tiling (mma.sync path — base ISA only; tcgen05 rejected by compute_103)
// TM=256/TN=64, warp grid 4x2: each warp = 64 rows x 32 cols (one proto group)
#define TM 256
#define TN 64
#define TK 32
#define NSTAGE 3
#define SA_STRIDE 40   // 32 + 8 pad (halves)
#define SB_STRIDE 40
#define A_STAGE_BYTES (TM * SA_STRIDE * 2)              // 20480
#define STAGE_BYTES (A_STAGE_BYTES + TN * SB_STRIDE * 2) // 25600
#define SMEM_TOTAL (NSTAGE * STAGE_BYTES)                // 76800

// Scratch (allocation-free rule: __device__ globals)
__device__ __align__(16) __half g_imgN[BATCH * HW * CDIM];   // [b*HW+hw][c]
__device__ __align__(16) __half g_protoN[NK * CDIM];         // [n*K+k][c]

// ---------------------------------------------------------------------------
// Kernel 1 (fused prep): blocks [0,600) normalize proto rows; blocks
// [600, 600+256) normalize+transpose the image. 256 threads everywhere.
// ---------------------------------------------------------------------------
__global__ void prep_kernel(const float* __restrict__ proto,
                            const float* __restrict__ img) {
    __shared__ float part[8][32];
    __shared__ float rn[32];
    __shared__ __half tile[32][520];

    if (blockIdx.x < 600) {
        int gwid = (blockIdx.x * 256 + threadIdx.x) >> 5;
        int lane = threadIdx.x & 31;
        const float4* row = reinterpret_cast<const float4*>(proto + (size_t)gwid * CDIM);
        float4 v[4];
        float ss = 0.f;
#pragma unroll
        for (int i = 0; i < 4; i++) {
            v[i] = row[lane + i * 32];
            ss += v[i].x * v[i].x + v[i].y * v[i].y + v[i].z * v[i].z + v[i].w * v[i].w;
        }
#pragma unroll
        for (int o = 16; o > 0; o >>= 1) ss += __shfl_xor_sync(0xffffffff, ss, o);
        float r = rsqrtf(ss + 1e-12f);
        __half2* dst = reinterpret_cast<__half2*>(g_protoN + (size_t)gwid * CDIM);
#pragma unroll
        for (int i = 0; i < 4; i++) {
            dst[(lane + i * 32) * 2]     = __floats2half2_rn(v[i].x * r, v[i].y * r);
            dst[(lane + i * 32) * 2 + 1] = __floats2half2_rn(v[i].z * r, v[i].w * r);
        }
        return;
    }

    int blk = blockIdx.x - 600;          // 0..255
    int tx = threadIdx.x & 31;
    int ty = threadIdx.x >> 5;
    int b = blk >> 5;
    int hw0 = (blk & 31) * 32;
    const float* base = img + (size_t)b * CDIM * HW + hw0 + tx;

    float ss = 0.f;
    for (int c = ty; c < CDIM; c += 8) {
        float v = base[(size_t)c * HW];
        ss += v * v;
    }
    part[ty][tx] = ss;
    __syncthreads();
    if (ty == 0) {
        float s = 0.f;
#pragma unroll
        for (int j = 0; j < 8; j++) s += part[j][tx];
        rn[tx] = rsqrtf(s + 1e-12f);
    }
    __syncthreads();
    float r = rn[tx];
    for (int c = ty; c < CDIM; c += 8) {
        float v = base[(size_t)c * HW];
        tile[tx][c] = __float2half(v * r);
    }
    __syncthreads();
#pragma unroll
    for (int it = 0; it < 4; it++) {
        int p = it * 8 + ty;
        const uint4* s = reinterpret_cast<const uint4*>(&tile[p][0]);
        uint4 d0 = s[tx * 2];
        uint4 d1 = s[tx * 2 + 1];
        uint4* dst = reinterpret_cast<uint4*>(g_imgN + ((size_t)(b * HW + hw0 + p)) * CDIM);
        dst[tx * 2]     = d0;
        dst[tx * 2 + 1] = d1;
    }
}

// ---------------------------------------------------------------------------
// Kernel 2: fused GEMM + warp-internal group max/mean + sigmoid
// TM=256 x TN=64, 3-stage cp.async pipeline, register-only epilogue.
// ---------------------------------------------------------------------------
__device__ __forceinline__ void cp_async16(uint32_t dst, const void* src) {
    asm volatile("cp.async.cg.shared.global [%0], [%1], 16;\n" :: "r"(dst), "l"(src));
}

__device__ __forceinline__ void load_chunk(const __half* gA, const __half* gB,
                                           uint32_t sbase, int s, int k0, int tid) {
    uint32_t abase = sbase + s * STAGE_BYTES;
    // A: 256 rows, one thread per row, 4 x 16B
    {
        const __half* src = gA + (size_t)tid * CDIM + k0;
        uint32_t d = abase + tid * (SA_STRIDE * 2);
#pragma unroll
        for (int c = 0; c < 4; c++)
            cp_async16(d + c * 16, src + c * 8);
    }
    // B: 64 rows, 4 threads per row, 1 x 16B each
    {
        int brow = tid >> 2;
        int bc = tid & 3;
        uint32_t bbase = abase + A_STAGE_BYTES;
        cp_async16(bbase + brow * (SB_STRIDE * 2) + bc * 16,
                   gB + (size_t)brow * CDIM + k0 + bc * 8);
    }
    asm volatile("cp.async.commit_group;\n");
}

__global__ __launch_bounds__(256, 2) void simgemm_kernel(float* __restrict__ out) {
    extern __shared__ char smem[];
    uint32_t sbase = (uint32_t)__cvta_generic_to_shared(smem);

    int tid  = threadIdx.x;
    int lane = tid & 31;
    int wid  = tid >> 5;
    int b    = blockIdx.z;
    int hw0  = blockIdx.y * TM;
    int col0 = blockIdx.x * TN;   // 2 whole protos per block

    const __half* gA = g_imgN   + ((size_t)(b * HW + hw0)) * CDIM;
    const __half* gB = g_protoN + (size_t)col0 * CDIM;

    int wm = wid >> 1;            // 0..3 : 64-px slice
    int wn = wid & 1;             // 0..1 : 32-col slice (one proto)
    int pxw = wm * 64;
    int clw = wn * 32;

    // ldmatrix per-lane coordinates (same mapping as validated R2 kernel)
    int a_r = lane & 15;
    int a_k = (lane >> 4) * 8;
    int b_r = (lane & 7) + ((lane >> 4) << 3);
    int b_k = ((lane >> 3) & 1) * 8;

    float acc[4][4][4];
#pragma unroll
    for (int mt = 0; mt < 4; mt++)
#pragma unroll
        for (int nt = 0; nt < 4; nt++)
#pragma unroll
            for (int i = 0; i < 4; i++) acc[mt][nt][i] = 0.f;

    const int NCHUNK = CDIM / TK;  // 16

    load_chunk(gA, gB, sbase, 0, 0, tid);
    load_chunk(gA, gB, sbase, 1, TK, tid);

    int stage = 0;
    for (int kc = 0; kc < NCHUNK; kc++) {
        if (kc == NCHUNK - 1) { asm volatile("cp.async.wait_group 0;\n"); }
        else                  { asm volatile("cp.async.wait_group 1;\n"); }
        __syncthreads();   // stage kc visible; protects buffer (kc+2)%3

        if (kc + 2 < NCHUNK) {
            int ps = stage + 2 >= NSTAGE ? stage + 2 - NSTAGE : stage + 2;
            load_chunk(gA, gB, sbase, ps, (kc + 2) * TK, tid);
        }

        uint32_t abase = sbase + stage * STAGE_BYTES;
        uint32_t bbase = abase + A_STAGE_BYTES;
#pragma unroll
        for (int ks = 0; ks < 2; ks++) {
            int kk = ks * 16;
            uint32_t af[4][4];
#pragma unroll
            for (int mt = 0; mt < 4; mt++) {
                uint32_t addr = abase + ((pxw + mt * 16 + a_r) * SA_STRIDE + kk + a_k) * 2;
                asm volatile("ldmatrix.sync.aligned.m8n8.x4.shared.b16 {%0,%1,%2,%3}, [%4];"
                             : "=r"(af[mt][0]), "=r"(af[mt][1]), "=r"(af[mt][2]), "=r"(af[mt][3])
                             : "r"(addr));
            }
            uint32_t bf[2][4];
#pragma unroll
            for (int i = 0; i < 2; i++) {
                uint32_t addr = bbase + ((clw + i * 16 + b_r) * SB_STRIDE + kk + b_k) * 2;
                asm volatile("ldmatrix.sync.aligned.m8n8.x4.shared.b16 {%0,%1,%2,%3}, [%4];"
                             : "=r"(bf[i][0]), "=r"(bf[i][1]), "=r"(bf[i][2]), "=r"(bf[i][3])
                             : "r"(addr));
            }
#pragma unroll
            for (int mt = 0; mt < 4; mt++)
#pragma unroll
                for (int nt = 0; nt < 4; nt++) {
                    int i = nt >> 1, j = (nt & 1) * 2;
                    asm volatile(
                        "mma.sync.aligned.m16n8k16.row.col.f32.f16.f16.f32 "
                        "{%0,%1,%2,%3}, {%4,%5,%6,%7}, {%8,%9}, {%0,%1,%2,%3};"
                        : "+f"(acc[mt][nt][0]), "+f"(acc[mt][nt][1]),
                          "+f"(acc[mt][nt][2]), "+f"(acc[mt][nt][3])
                        : "r"(af[mt][0]), "r"(af[mt][1]), "r"(af[mt][2]), "r"(af[mt][3]),
                          "r"(bf[i][j]), "r"(bf[i][j + 1]));
                }
        }
        stage = stage + 1 == NSTAGE ? 0 : stage + 1;
    }

    // Register-only epilogue: warp owns one proto (32 cols) x 64 rows.
    // Row r of each 4-lane group holds cols {nt*8 + (lane&3)*2 + 0,1}.
    int ng = (col0 >> 5) + wn;
    size_t obase = ((size_t)(b * NPROTO + ng)) * HW;
    size_t splane = (size_t)BATCH * NPROTO * HW;

#pragma unroll
    for (int mt = 0; mt < 4; mt++) {
        float mx0 = -1e30f, s0 = 0.f, mx1 = -1e30f, s1 = 0.f;
#pragma unroll
        for (int nt = 0; nt < 4; nt++) {
            mx0 = fmaxf(mx0, fmaxf(acc[mt][nt][0], acc[mt][nt][1]));
            s0 += acc[mt][nt][0] + acc[mt][nt][1];
            mx1 = fmaxf(mx1, fmaxf(acc[mt][nt][2], acc[mt][nt][3]));
            s1 += acc[mt][nt][2] + acc[mt][nt][3];
        }
        // butterfly over the 4-lane row group (lanes 4q..4q+3)
#pragma unroll
        for (int o = 1; o <= 2; o <<= 1) {
            mx0 = fmaxf(mx0, __shfl_xor_sync(0xffffffff, mx0, o));
            s0 += __shfl_xor_sync(0xffffffff, s0, o);
            mx1 = fmaxf(mx1, __shfl_xor_sync(0xffffffff, mx1, o));
            s1 += __shfl_xor_sync(0xffffffff, s1, o);
        }
        float sim0  = 0.5f * mx0 + 0.5f * (s0 * (1.0f / 32.0f));
        float sim1  = 0.5f * mx1 + 0.5f * (s1 * (1.0f / 32.0f));
        float mask0 = 1.0f / (1.0f + __expf(-sim0));
        float mask1 = 1.0f / (1.0f + __expf(-sim1));

        int sel = lane & 3;
        int rbase = hw0 + pxw + mt * 16 + (lane >> 2);
        if (sel == 0) {
            out[obase + rbase] = mask0;
            out[obase + rbase + splane] = sim0;
        } else if (sel == 1) {
            out[obase + rbase + 8] = mask1;
            out[obase + rbase + 8 + splane] = sim1;
        }
    }
}

// ---------------------------------------------------------------------------
extern "C" void kernel_launch(void* const* d_in, const int* in_sizes, int n_in,
                              void* d_out, int out_size) {
    (void)in_sizes; (void)n_in; (void)out_size;
    const float* img   = (const float*)d_in[0];   // [8,512,32,32]
    const float* proto = (const float*)d_in[1];   // [150,32,512]
    float* out = (float*)d_out;

    cudaFuncSetAttribute(simgemm_kernel,
                         cudaFuncAttributeMaxDynamicSharedMemorySize, SMEM_TOTAL);

    prep_kernel<<<600 + 256, 256>>>(proto, img);
    simgemm_kernel<<<dim3(NK / TN, HW / TM, BATCH), 256, SMEM_TOTAL>>>(out);
}

// round 14
// speedup vs baseline: 1.4941x; 1.4941x over previous
#include <cuda_runtime.h>
#include <cuda_fp16.h>
#include <cstdint>

// Problem constants
#define BATCH 8
#define CDIM 512
#define HW   1024
#define NPROTO 150
#define KPROTO 32
#define NK   4800   // NPROTO * KPROTO

// GEMM tiling (mma.sync path — base ISA only; tcgen05 rejected by compute_103)
// TM=128/TN=64, warp grid 4x2: each warp = 32 rows x 32 cols (one proto group)
#define TM 128
#define TN 64
#define TK 32
#define NSTAGE 3
#define SA_STRIDE 40   // 32 + 8 pad (halves)
#define SB_STRIDE 40

// Scratch (allocation-free rule: __device__ globals)
__device__ __align__(16) __half g_imgN[BATCH * HW * CDIM];   // [b*HW+hw][c]
__device__ __align__(16) __half g_protoN[NK * CDIM];         // [n*K+k][c]

// ---------------------------------------------------------------------------
// Kernel 1 (fused prep): blocks [0,600) normalize proto rows; blocks
// [600, 600+256) normalize+transpose the image. 256 threads everywhere.
// ---------------------------------------------------------------------------
__global__ void prep_kernel(const float* __restrict__ proto,
                            const float* __restrict__ img) {
    __shared__ float part[8][32];
    __shared__ float rn[32];
    __shared__ __half tile[32][520];

    if (blockIdx.x < 600) {
        int gwid = (blockIdx.x * 256 + threadIdx.x) >> 5;
        int lane = threadIdx.x & 31;
        const float4* row = reinterpret_cast<const float4*>(proto + (size_t)gwid * CDIM);
        float4 v[4];
        float ss = 0.f;
#pragma unroll
        for (int i = 0; i < 4; i++) {
            v[i] = row[lane + i * 32];
            ss += v[i].x * v[i].x + v[i].y * v[i].y + v[i].z * v[i].z + v[i].w * v[i].w;
        }
#pragma unroll
        for (int o = 16; o > 0; o >>= 1) ss += __shfl_xor_sync(0xffffffff, ss, o);
        float r = rsqrtf(ss + 1e-12f);
        __half2* dst = reinterpret_cast<__half2*>(g_protoN + (size_t)gwid * CDIM);
#pragma unroll
        for (int i = 0; i < 4; i++) {
            dst[(lane + i * 32) * 2]     = __floats2half2_rn(v[i].x * r, v[i].y * r);
            dst[(lane + i * 32) * 2 + 1] = __floats2half2_rn(v[i].z * r, v[i].w * r);
        }
        return;
    }

    int blk = blockIdx.x - 600;          // 0..255
    int tx = threadIdx.x & 31;
    int ty = threadIdx.x >> 5;
    int b = blk >> 5;
    int hw0 = (blk & 31) * 32;
    const float* base = img + (size_t)b * CDIM * HW + hw0 + tx;

    float ss = 0.f;
    for (int c = ty; c < CDIM; c += 8) {
        float v = base[(size_t)c * HW];
        ss += v * v;
    }
    part[ty][tx] = ss;
    __syncthreads();
    if (ty == 0) {
        float s = 0.f;
#pragma unroll
        for (int j = 0; j < 8; j++) s += part[j][tx];
        rn[tx] = rsqrtf(s + 1e-12f);
    }
    __syncthreads();
    float r = rn[tx];
    for (int c = ty; c < CDIM; c += 8) {
        float v = base[(size_t)c * HW];
        tile[tx][c] = __float2half(v * r);
    }
    __syncthreads();
#pragma unroll
    for (int it = 0; it < 4; it++) {
        int p = it * 8 + ty;
        const uint4* s = reinterpret_cast<const uint4*>(&tile[p][0]);
        uint4 d0 = s[tx * 2];
        uint4 d1 = s[tx * 2 + 1];
        uint4* dst = reinterpret_cast<uint4*>(g_imgN + ((size_t)(b * HW + hw0 + p)) * CDIM);
        dst[tx * 2]     = d0;
        dst[tx * 2 + 1] = d1;
    }
}

// ---------------------------------------------------------------------------
// Kernel 2: fused GEMM + warp-internal group max/mean + sigmoid
// TM=128 x TN=64, warps 4x2, 3-stage cp.async pipeline, register epilogue.
// ---------------------------------------------------------------------------
struct SMemOp {
    __half A[NSTAGE][TM * SA_STRIDE];   // 3 * 5120 halves = 30720 B
    __half B[NSTAGE][TN * SB_STRIDE];   // 3 * 2560 halves = 15360 B
};

__device__ __forceinline__ void cp_async16(uint32_t dst, const void* src) {
    asm volatile("cp.async.cg.shared.global [%0], [%1], 16;\n" :: "r"(dst), "l"(src));
}

__device__ __forceinline__ void load_chunk(const __half* gA, const __half* gB,
                                           __half* sA, __half* sB, int k0, int tid) {
    int ar = tid >> 2;            // 0..63
    int ac = (tid & 3) * 8;       // half offset within 32-chunk
    uint32_t sa = (uint32_t)__cvta_generic_to_shared(sA);
    cp_async16(sa + ((ar)      * SA_STRIDE + ac) * 2, gA + (size_t)(ar)      * CDIM + k0 + ac);
    cp_async16(sa + ((ar + 64) * SA_STRIDE + ac) * 2, gA + (size_t)(ar + 64) * CDIM + k0 + ac);
    uint32_t sb = (uint32_t)__cvta_generic_to_shared(sB);
    cp_async16(sb + (ar * SB_STRIDE + ac) * 2,        gB + (size_t)ar * CDIM + k0 + ac);
    asm volatile("cp.async.commit_group;\n");
}

__global__ __launch_bounds__(256) void simgemm_kernel(float* __restrict__ out) {
    __shared__ SMemOp sm;

    int tid  = threadIdx.x;
    int lane = tid & 31;
    int wid  = tid >> 5;
    int b    = blockIdx.z;
    int hw0  = blockIdx.y * TM;
    int col0 = blockIdx.x * TN;   // 2 whole protos per block

    const __half* gA = g_imgN   + ((size_t)(b * HW + hw0)) * CDIM;
    const __half* gB = g_protoN + (size_t)col0 * CDIM;

    int wm = wid >> 1;            // 0..3 : 32-px slice
    int wn = wid & 1;             // 0..1 : 32-col slice (one proto)
    int pxw = wm * 32;
    int clw = wn * 32;

    // ldmatrix per-lane coordinates (validated mapping)
    int a_r = lane & 15;
    int a_k = (lane >> 4) * 8;
    int b_r = (lane & 7) + ((lane >> 4) << 3);
    int b_k = ((lane >> 3) & 1) * 8;

    float acc[2][4][4];
#pragma unroll
    for (int mt = 0; mt < 2; mt++)
#pragma unroll
        for (int nt = 0; nt < 4; nt++)
#pragma unroll
            for (int i = 0; i < 4; i++) acc[mt][nt][i] = 0.f;

    const int NCHUNK = CDIM / TK;  // 16

    load_chunk(gA, gB, sm.A[0], sm.B[0], 0, tid);
    load_chunk(gA, gB, sm.A[1], sm.B[1], TK, tid);

    int stage = 0;
    for (int kc = 0; kc < NCHUNK; kc++) {
        if (kc == NCHUNK - 1) { asm volatile("cp.async.wait_group 0;\n"); }
        else                  { asm volatile("cp.async.wait_group 1;\n"); }
        __syncthreads();   // stage kc visible; protects buffer (kc+2)%3

        if (kc + 2 < NCHUNK) {
            int ps = stage + 2 >= NSTAGE ? stage + 2 - NSTAGE : stage + 2;
            load_chunk(gA, gB, sm.A[ps], sm.B[ps], (kc + 2) * TK, tid);
        }

        const __half* sA = sm.A[stage];
        const __half* sB = sm.B[stage];
#pragma unroll
        for (int ks = 0; ks < 2; ks++) {
            int kk = ks * 16;
            uint32_t af[2][4];
#pragma unroll
            for (int mt = 0; mt < 2; mt++) {
                uint32_t addr = (uint32_t)__cvta_generic_to_shared(
                    sA + (size_t)(pxw + mt * 16 + a_r) * SA_STRIDE + kk + a_k);
                asm volatile("ldmatrix.sync.aligned.m8n8.x4.shared.b16 {%0,%1,%2,%3}, [%4];"
                             : "=r"(af[mt][0]), "=r"(af[mt][1]), "=r"(af[mt][2]), "=r"(af[mt][3])
                             : "r"(addr));
            }
            uint32_t bf[2][4];
#pragma unroll
            for (int i = 0; i < 2; i++) {
                uint32_t addr = (uint32_t)__cvta_generic_to_shared(
                    sB + (size_t)(clw + i * 16 + b_r) * SB_STRIDE + kk + b_k);
                asm volatile("ldmatrix.sync.aligned.m8n8.x4.shared.b16 {%0,%1,%2,%3}, [%4];"
                             : "=r"(bf[i][0]), "=r"(bf[i][1]), "=r"(bf[i][2]), "=r"(bf[i][3])
                             : "r"(addr));
            }
#pragma unroll
            for (int mt = 0; mt < 2; mt++)
#pragma unroll
                for (int nt = 0; nt < 4; nt++) {
                    int i = nt >> 1, j = (nt & 1) * 2;
                    asm volatile(
                        "mma.sync.aligned.m16n8k16.row.col.f32.f16.f16.f32 "
                        "{%0,%1,%2,%3}, {%4,%5,%6,%7}, {%8,%9}, {%0,%1,%2,%3};"
                        : "+f"(acc[mt][nt][0]), "+f"(acc[mt][nt][1]),
                          "+f"(acc[mt][nt][2]), "+f"(acc[mt][nt][3])
                        : "r"(af[mt][0]), "r"(af[mt][1]), "r"(af[mt][2]), "r"(af[mt][3]),
                          "r"(bf[i][j]), "r"(bf[i][j + 1]));
                }
        }
        stage = stage + 1 == NSTAGE ? 0 : stage + 1;
    }

    // Register-only epilogue (validated in R12): warp owns one proto (32 cols)
    // x 32 rows. Row r of each 4-lane group holds cols {nt*8+(lane&3)*2+0,1}.
    int ng = (col0 >> 5) + wn;
    size_t obase = ((size_t)(b * NPROTO + ng)) * HW;
    size_t splane = (size_t)BATCH * NPROTO * HW;

#pragma unroll
    for (int mt = 0; mt < 2; mt++) {
        float mx0 = -1e30f, s0 = 0.f, mx1 = -1e30f, s1 = 0.f;
#pragma unroll
        for (int nt = 0; nt < 4; nt++) {
            mx0 = fmaxf(mx0, fmaxf(acc[mt][nt][0], acc[mt][nt][1]));
            s0 += acc[mt][nt][0] + acc[mt][nt][1];
            mx1 = fmaxf(mx1, fmaxf(acc[mt][nt][2], acc[mt][nt][3]));
            s1 += acc[mt][nt][2] + acc[mt][nt][3];
        }
        // butterfly over the 4-lane row group (lanes 4q..4q+3)
#pragma unroll
        for (int o = 1; o <= 2; o <<= 1) {
            mx0 = fmaxf(mx0, __shfl_xor_sync(0xffffffff, mx0, o));
            s0 += __shfl_xor_sync(0xffffffff, s0, o);
            mx1 = fmaxf(mx1, __shfl_xor_sync(0xffffffff, mx1, o));
            s1 += __shfl_xor_sync(0xffffffff, s1, o);
        }
        float sim0  = 0.5f * mx0 + 0.5f * (s0 * (1.0f / 32.0f));
        float sim1  = 0.5f * mx1 + 0.5f * (s1 * (1.0f / 32.0f));
        float mask0 = 1.0f / (1.0f + __expf(-sim0));
        float mask1 = 1.0f / (1.0f + __expf(-sim1));

        int sel = lane & 3;
        int rbase = hw0 + pxw + mt * 16 + (lane >> 2);
        if (sel == 0) {
            out[obase + rbase] = mask0;
            out[obase + rbase + splane] = sim0;
        } else if (sel == 1) {
            out[obase + rbase + 8] = mask1;
            out[obase + rbase + 8 + splane] = sim1;
        }
    }
}

// ---------------------------------------------------------------------------
extern "C" void kernel_launch(void* const* d_in, const int* in_sizes, int n_in,
                              void* d_out, int out_size) {
    (void)in_sizes; (void)n_in; (void)out_size;
    const float* img   = (const float*)d_in[0];   // [8,512,32,32]
    const float* proto = (const float*)d_in[1];   // [150,32,512]
    float* out = (float*)d_out;

    prep_kernel<<<600 + 256, 256>>>(proto, img);
    simgemm_kernel<<<dim3(NK / TN, HW / TM, BATCH), 256>>>(out);
}